// round 4
// baseline (speedup 1.0000x reference)
#include <cuda_runtime.h>
#include <cstdint>
#include <cstddef>

// RNN_49297634623576: out = fc_w @ tanh(w_ih @ x[:,27,:] + b_ih + b_hh) + fc_b
// hx == 0 => w_hh unused.
//
// R4: the binder is resident parallelism (occ 10%, issue 27%, no pipe >31%).
// Total warps were capped at NB/(32*RPT). Fix: split each batch row across
// TWO threads (each owns 32 of the 64 hidden units) -> 131072 threads,
// 4096 warps (6.9/SMSP), 1024 small CTAs (no wave quantization). Halves
// combine FC partials with 10 SHFL + 5 f32x2 adds; even lane stores.

#define NB   65536
#define NIN  28
#define NHID 64
#define NOUT 10
#define TPB  128   // 64 rows/CTA (2 threads/row) -> 1024 CTAs

typedef unsigned long long u64;

__device__ __forceinline__ u64 pk2(float a, float b) {
    u64 r; asm("mov.b64 %0,{%1,%2};" : "=l"(r) : "f"(a), "f"(b)); return r;
}
__device__ __forceinline__ void upk2(u64 v, float& a, float& b) {
    asm("mov.b64 {%0,%1},%2;" : "=f"(a), "=f"(b) : "l"(v));
}
__device__ __forceinline__ u64 ffma2(u64 a, u64 b, u64 c) {
    u64 d; asm("fma.rn.f32x2 %0,%1,%2,%3;" : "=l"(d) : "l"(a), "l"(b), "l"(c)); return d;
}
__device__ __forceinline__ u64 fadd2(u64 a, u64 b) {
    u64 d; asm("add.rn.f32x2 %0,%1,%2;" : "=l"(d) : "l"(a), "l"(b)); return d;
}
__device__ __forceinline__ float hsum2(u64 v) {
    float a, b; upk2(v, a, b); return a + b;
}

// tanh(x) = 1 - 2*rcp(exp2(x*2log2e)+1)
__device__ __forceinline__ float tanh_fast(float x) {
    const float LOG2E_X2 = 2.8853900817779268f;
    float e, r;
    asm("ex2.approx.ftz.f32 %0, %1;" : "=f"(e) : "f"(x * LOG2E_X2));
    asm("rcp.approx.ftz.f32 %0, %1;" : "=f"(r) : "f"(e + 1.0f));
    return fmaf(-2.0f, r, 1.0f);
}

__global__ void __launch_bounds__(TPB, 5)
rnn_fused_kernel(const float* __restrict__ x,
                 const float* __restrict__ w_ih,
                 const float* __restrict__ b_ih,
                 const float* __restrict__ b_hh,
                 const float* __restrict__ fc_w,
                 const float* __restrict__ fc_b,
                 float* __restrict__ out)
{
    // [j][0..13] = {w[j][2p], w[j][2p+1]}, [j][14] = {bias_j, 0}, [15] pad
    __shared__ u64 s_wb[NHID][16];
    // [j][q] = {fc_w[2q][j], fc_w[2q+1][j]}, padded to 6 for 16B row alignment
    __shared__ u64 s_fck[NHID][6];
    __shared__ u64 s_fcb[NOUT / 2];

    const int tid = threadIdx.x;

    for (int i = tid; i < NHID * (NIN / 2); i += TPB) {
        int j = i / (NIN / 2), p = i % (NIN / 2);
        s_wb[j][p] = pk2(w_ih[j * NIN + 2 * p], w_ih[j * NIN + 2 * p + 1]);
    }
    for (int i = tid; i < NHID; i += TPB) s_wb[i][14] = pk2(b_ih[i] + b_hh[i], 0.0f);
    for (int i = tid; i < NHID * (NOUT / 2); i += TPB) {
        int j = i / (NOUT / 2), q = i % (NOUT / 2);
        s_fck[j][q] = pk2(fc_w[(2 * q) * NHID + j], fc_w[(2 * q + 1) * NHID + j]);
    }
    if (tid < NOUT / 2) s_fcb[tid] = pk2(fc_b[2 * tid], fc_b[2 * tid + 1]);
    __syncthreads();

    const int row   = blockIdx.x * (TPB / 2) + (tid >> 1);  // 64 rows per CTA
    const int half  = tid & 1;
    const int jbase = half << 5;                            // 0 or 32

    // Load this row's last 28 floats (both halves load; coalescer dedups pairs).
    u64 in[NIN / 2];
    {
        const float4* p = reinterpret_cast<const float4*>(x + (size_t)row * 784 + 756);
#pragma unroll
        for (int q = 0; q < 7; q++) {
            float4 v = p[q];
            in[2 * q]     = pk2(v.x, v.y);
            in[2 * q + 1] = pk2(v.z, v.w);
        }
    }

    // FC accumulators {out[2q], out[2q+1]}; only even half carries fc bias.
    u64 oa[NOUT / 2];
#pragma unroll
    for (int q = 0; q < NOUT / 2; q++) oa[q] = half ? 0ull : s_fcb[q];

#pragma unroll 1
    for (int jj = 0; jj < 32; jj += 2) {
        const int j0 = jbase + jj, j1 = j0 + 1;
        u64 a0 = s_wb[j0][14];   // {bias, 0}
        u64 a1 = s_wb[j1][14];
#pragma unroll
        for (int p = 0; p < NIN / 2; p++) {
            a0 = ffma2(s_wb[j0][p], in[p], a0);
            a1 = ffma2(s_wb[j1][p], in[p], a1);
        }
        float h0 = tanh_fast(hsum2(a0));
        float h1 = tanh_fast(hsum2(a1));
        u64 hp0 = pk2(h0, h0);
        u64 hp1 = pk2(h1, h1);
#pragma unroll
        for (int q = 0; q < NOUT / 2; q++) {
            oa[q] = ffma2(s_fck[j0][q], hp0, oa[q]);
            oa[q] = ffma2(s_fck[j1][q], hp1, oa[q]);
        }
    }

    // Combine the two halves (lanes 2k, 2k+1) and store from the even lane.
#pragma unroll
    for (int q = 0; q < NOUT / 2; q++) {
        u64 other = __shfl_down_sync(0xffffffffu, oa[q], 1);
        oa[q] = fadd2(oa[q], other);
    }
    if (half == 0) {
        float2* o2 = reinterpret_cast<float2*>(out + (size_t)row * NOUT);
#pragma unroll
        for (int q = 0; q < NOUT / 2; q++) {
            float a, b;
            upk2(oa[q], a, b);
            o2[q] = make_float2(a, b);
        }
    }
}

extern "C" void kernel_launch(void* const* d_in, const int* in_sizes, int n_in,
                              void* d_out, int out_size)
{
    (void)in_sizes; (void)n_in; (void)out_size;
    const float* x    = (const float*)d_in[0];
    const float* w_ih = (const float*)d_in[1];
    // d_in[2] = w_hh : unused (hx == 0)
    const float* b_ih = (const float*)d_in[3];
    const float* b_hh = (const float*)d_in[4];
    const float* fc_w = (const float*)d_in[5];
    const float* fc_b = (const float*)d_in[6];
    float* out = (float*)d_out;

    const int blocks = NB / (TPB / 2);   // 1024, exact

    rnn_fused_kernel<<<blocks, TPB>>>(x, w_ih, b_ih, b_hh, fc_w, fc_b, out);
}

// round 5
// speedup vs baseline: 1.4443x; 1.4443x over previous
#include <cuda_runtime.h>
#include <cstdint>
#include <cstddef>

// RNN_49297634623576: out = fc_w @ tanh(w_ih @ x[:,27,:] + b_ih + b_hh) + fc_b
// hx == 0 => w_hh unused.
//
// R5: R4's lane-split broke warp-uniform LDS (2-addr, systematically
// bank-conflicted: L1 69.5%). Revert to unsplit rows (every LDS is a
// single-address broadcast, conflict-free by construction), but take the
// warp-count win properly: RPT=1 -> 2048 warps (3.46/SMSP), 512 CTAs,
// 6 CTAs/SM. Cut LDS issues ~45% with LDS.128 weight loads (7/j not 14).

#define NB   65536
#define NIN  28
#define NHID 64
#define NOUT 10
#define TPB  128   // 1 row/thread -> 512 CTAs

typedef unsigned long long u64;

__device__ __forceinline__ u64 pk2(float a, float b) {
    u64 r; asm("mov.b64 %0,{%1,%2};" : "=l"(r) : "f"(a), "f"(b)); return r;
}
__device__ __forceinline__ void upk2(u64 v, float& a, float& b) {
    asm("mov.b64 {%0,%1},%2;" : "=f"(a), "=f"(b) : "l"(v));
}
__device__ __forceinline__ u64 ffma2(u64 a, u64 b, u64 c) {
    u64 d; asm("fma.rn.f32x2 %0,%1,%2,%3;" : "=l"(d) : "l"(a), "l"(b), "l"(c)); return d;
}
__device__ __forceinline__ float hsum2(u64 v) {
    float a, b; upk2(v, a, b); return a + b;
}

// tanh(x) = 1 - 2*rcp(exp2(x*2log2e)+1); ~1e-6 accurate.
__device__ __forceinline__ float tanh_fast(float x) {
    const float LOG2E_X2 = 2.8853900817779268f;
    float e, r;
    asm("ex2.approx.ftz.f32 %0, %1;" : "=f"(e) : "f"(x * LOG2E_X2));
    asm("rcp.approx.ftz.f32 %0, %1;" : "=f"(r) : "f"(e + 1.0f));
    return fmaf(-2.0f, r, 1.0f);
}

__global__ void __launch_bounds__(TPB, 6)
rnn_fused_kernel(const float* __restrict__ x,
                 const float* __restrict__ w_ih,
                 const float* __restrict__ b_ih,
                 const float* __restrict__ b_hh,
                 const float* __restrict__ fc_w,
                 const float* __restrict__ fc_b,
                 float* __restrict__ out)
{
    // Row j (128B, 16B-aligned): [0..13]={w[j][2p],w[j][2p+1]}, [14]={bias_j,0}, [15] pad.
    __shared__ u64 s_w[NHID][16];
    // Row j (48B): [q<5]={fc_w[2q][j], fc_w[2q+1][j]}, [5] pad.
    __shared__ u64 s_fck[NHID][6];
    __shared__ u64 s_fcb[NOUT / 2];

    const int tid = threadIdx.x;

    for (int i = tid; i < NHID * (NIN / 2); i += TPB) {
        int j = i / (NIN / 2), p = i % (NIN / 2);
        s_w[j][p] = pk2(w_ih[j * NIN + 2 * p], w_ih[j * NIN + 2 * p + 1]);
    }
    for (int i = tid; i < NHID; i += TPB) {
        s_w[i][14] = pk2(b_ih[i] + b_hh[i], 0.0f);
        s_w[i][15] = 0ull;
    }
    for (int i = tid; i < NHID * (NOUT / 2); i += TPB) {
        int j = i / (NOUT / 2), q = i % (NOUT / 2);
        s_fck[j][q] = pk2(fc_w[(2 * q) * NHID + j], fc_w[(2 * q + 1) * NHID + j]);
    }
    for (int i = tid; i < NHID; i += TPB) s_fck[i][5] = 0ull;
    if (tid < NOUT / 2) s_fcb[tid] = pk2(fc_b[2 * tid], fc_b[2 * tid + 1]);
    __syncthreads();

    const int row = blockIdx.x * TPB + tid;   // one batch row per thread

    // Last 28 floats of this row; float offset 756 is 16B aligned.
    u64 in[NIN / 2];
    {
        const float4* p = reinterpret_cast<const float4*>(x + (size_t)row * 784 + 756);
#pragma unroll
        for (int q = 0; q < 7; q++) {
            float4 v = p[q];
            in[2 * q]     = pk2(v.x, v.y);
            in[2 * q + 1] = pk2(v.z, v.w);
        }
    }

    // FC accumulators {out[2q], out[2q+1]}, fc bias pre-folded.
    u64 oa[NOUT / 2];
#pragma unroll
    for (int q = 0; q < NOUT / 2; q++) oa[q] = s_fcb[q];

#pragma unroll 1
    for (int jj = 0; jj < NHID; jj += 2) {
        // Weight rows via LDS.128 (uniform broadcast, conflict-free): 8 loads for 2 j.
        const ulonglong2* r0 = reinterpret_cast<const ulonglong2*>(&s_w[jj][0]);
        const ulonglong2* r1 = reinterpret_cast<const ulonglong2*>(&s_w[jj + 1][0]);
        ulonglong2 w0[8], w1[8];
#pragma unroll
        for (int p = 0; p < 8; p++) { w0[p] = r0[p]; w1[p] = r1[p]; }

        u64 a0 = w0[7].x;   // {bias_j0, 0}
        u64 a1 = w1[7].x;   // {bias_j1, 0}
#pragma unroll
        for (int p = 0; p < 7; p++) {
            a0 = ffma2(w0[p].x, in[2 * p], a0);
            a0 = ffma2(w0[p].y, in[2 * p + 1], a0);
            a1 = ffma2(w1[p].x, in[2 * p], a1);
            a1 = ffma2(w1[p].y, in[2 * p + 1], a1);
        }
        float h0 = tanh_fast(hsum2(a0));
        float h1 = tanh_fast(hsum2(a1));
        u64 hp0 = pk2(h0, h0);
        u64 hp1 = pk2(h1, h1);

        // FC weights: 2x LDS.128 + 1x LDS.64 per j (uniform broadcast).
        const ulonglong2* f0 = reinterpret_cast<const ulonglong2*>(&s_fck[jj][0]);
        const ulonglong2* f1 = reinterpret_cast<const ulonglong2*>(&s_fck[jj + 1][0]);
        ulonglong2 fa = f0[0], fb = f0[1];
        ulonglong2 fc = f1[0], fd = f1[1];
        u64 fe = s_fck[jj][4], ff = s_fck[jj + 1][4];
        oa[0] = ffma2(fa.x, hp0, oa[0]);
        oa[1] = ffma2(fa.y, hp0, oa[1]);
        oa[2] = ffma2(fb.x, hp0, oa[2]);
        oa[3] = ffma2(fb.y, hp0, oa[3]);
        oa[4] = ffma2(fe,   hp0, oa[4]);
        oa[0] = ffma2(fc.x, hp1, oa[0]);
        oa[1] = ffma2(fc.y, hp1, oa[1]);
        oa[2] = ffma2(fd.x, hp1, oa[2]);
        oa[3] = ffma2(fd.y, hp1, oa[3]);
        oa[4] = ffma2(ff,   hp1, oa[4]);
    }

    // Store 10 floats = 5x STG.64 (40B row stride -> 8B aligned).
    {
        float2* o2 = reinterpret_cast<float2*>(out + (size_t)row * NOUT);
#pragma unroll
        for (int q = 0; q < NOUT / 2; q++) {
            float a, b;
            upk2(oa[q], a, b);
            o2[q] = make_float2(a, b);
        }
    }
}

extern "C" void kernel_launch(void* const* d_in, const int* in_sizes, int n_in,
                              void* d_out, int out_size)
{
    (void)in_sizes; (void)n_in; (void)out_size;
    const float* x    = (const float*)d_in[0];
    const float* w_ih = (const float*)d_in[1];
    // d_in[2] = w_hh : unused (hx == 0)
    const float* b_ih = (const float*)d_in[3];
    const float* b_hh = (const float*)d_in[4];
    const float* fc_w = (const float*)d_in[5];
    const float* fc_b = (const float*)d_in[6];
    float* out = (float*)d_out;

    const int blocks = NB / TPB;   // 512, exact

    rnn_fused_kernel<<<blocks, TPB>>>(x, w_ih, b_ih, b_hh, fc_w, fc_b, out);
}